// round 4
// baseline (speedup 1.0000x reference)
#include <cuda_runtime.h>
#include <cuda.h>
#include <cstdint>

// ---------------- problem constants ----------------
#define ROWG   64
#define IN_DIM 1024
#define OUT_D  1024
#define BATCH  512

// ---------------- tiling ----------------
#define BM 128
#define BN 128
#define BK 32
#define NK (IN_DIM / BK)   // 32
#define STG 3              // pipeline stages
#define BPAD 136           // B row stride in floats (conflict-free, from R1)

// ---------------- smem layout (relative to 1024-aligned base) ----------------
#define A_STAGE 16384                      // 128 rows x 128B (TMA SW128)
#define B_STAGE (BK * BPAD * 4)            // 17408
#define SM_A 0
#define SM_B (STG * A_STAGE)               // 49152
#define CTRL (SM_B + STG * B_STAGE)        // 101376
#define SMEM_BYTES (CTRL + 48 + 1024)      // barriers + align slack

// one-operand (B) tf32 truncation de-bias
static constexpr float KAPPA = 1.000352f;

// ---------------- PTX helpers ----------------
#define MBARRIER_INIT(addr, cnt) \
    asm volatile("mbarrier.init.shared.b64 [%0], %1;" :: "r"(addr), "r"(cnt) : "memory")

#define MBARRIER_EXPECT_TX(addr, bytes) \
    asm volatile("mbarrier.arrive.expect_tx.shared.b64 _, [%0], %1;" :: "r"(addr), "r"(bytes) : "memory")

#define MBARRIER_ARRIVE(addr) \
    asm volatile("mbarrier.arrive.shared::cta.b64 _, [%0];" :: "r"(addr) : "memory")

#define MBAR_WAIT(addr, parity) do {                                        \
    asm volatile(                                                           \
        "{\n\t.reg .pred P1;\n\t"                                           \
        "WAIT_LOOP_%=:\n\t"                                                 \
        "mbarrier.try_wait.parity.acquire.cta.shared::cta.b64 P1, [%0], %1, 0x989680;\n\t" \
        "@P1 bra.uni WAIT_DONE_%=;\n\t"                                     \
        "bra.uni WAIT_LOOP_%=;\n\t"                                         \
        "WAIT_DONE_%=:\n\t}"                                                \
        :: "r"(addr), "r"(parity) : "memory");                              \
} while (0)

#define TMA_LOAD_3D(smem_addr, map_ptr, cx, cy, cz, mbar) \
    asm volatile( \
        "cp.async.bulk.tensor.3d.shared::cta.global.tile.mbarrier::complete_tx::bytes " \
        "[%0], [%1, {%2, %3, %4}], [%5];" \
        :: "r"((uint32_t)(smem_addr)), "l"(map_ptr), \
           "r"((int)(cx)), "r"((int)(cy)), "r"((int)(cz)), \
           "r"((uint32_t)(mbar)) : "memory")

#define CPASYNC_ARRIVE(addr) \
    asm volatile("cp.async.mbarrier.arrive.noinc.shared::cta.b64 [%0];" :: "r"(addr) : "memory")

__device__ __forceinline__ void cp16(uint32_t dst, const float* src) {
    asm volatile("cp.async.cg.shared.global [%0], [%1], 16;" :: "r"(dst), "l"(src));
}

__device__ __forceinline__ uint32_t f2tf(float v) {
    uint32_t t;
    asm("cvt.rna.tf32.f32 %0, %1;" : "=r"(t) : "f"(v));
    return t;
}

__device__ __forceinline__ void mma_tf32(float* c, const uint32_t* a, const uint32_t* b) {
    asm volatile(
        "mma.sync.aligned.m16n8k8.row.col.f32.tf32.tf32.f32 "
        "{%0,%1,%2,%3}, {%4,%5,%6,%7}, {%8,%9}, {%0,%1,%2,%3};\n"
        : "+f"(c[0]), "+f"(c[1]), "+f"(c[2]), "+f"(c[3])
        : "r"(a[0]), "r"(a[1]), "r"(a[2]), "r"(a[3]),
          "r"(b[0]), "r"(b[1]));
}

// ---------------- kernel ----------------
__global__ __launch_bounds__(288, 2)
void gmlp_ws(const __grid_constant__ CUtensorMap tmA,
             const float* __restrict__ W,
             const float* __restrict__ bias,
             float* __restrict__ out)
{
    extern __shared__ char raw[];
    char* smp = (char*)(((uintptr_t)raw + 1023) & ~(uintptr_t)1023);
    const uint32_t sb = (uint32_t)__cvta_generic_to_shared(smp);
    float* smf = (float*)smp;

    const int tid  = threadIdx.x;
    const int wid  = tid >> 5;
    const int lane = tid & 31;
    const int n0 = blockIdx.x * BN;
    const int m0 = blockIdx.y * BM;
    const int r  = blockIdx.z;

    if (tid == 0) {
        #pragma unroll
        for (int s = 0; s < STG; s++) {
            MBARRIER_INIT(sb + CTRL + 8 * s, 33);       // full[s]: 32 cp.async + 1 expect_tx
            MBARRIER_INIT(sb + CTRL + 24 + 8 * s, 8);   // empty[s]: 8 consumer warps
        }
        asm volatile("fence.proxy.async.shared::cta;" ::: "memory");
    }
    __syncthreads();

    if (wid == 8) {
        // ---------------- producer warp ----------------
        const float* Wg = W + (size_t)r * IN_DIM * OUT_D + n0 + lane * 4;
        int s = 0, u = 0;
        for (int kt = 0; kt < NK; kt++) {
            const uint32_t full  = sb + CTRL + 8 * s;
            const uint32_t empty = sb + CTRL + 24 + 8 * s;
            if (kt >= STG) MBAR_WAIT(empty, u ^ 1);
            if (lane == 0) {
                MBARRIER_EXPECT_TX(full, A_STAGE);
                TMA_LOAD_3D(sb + SM_A + s * A_STAGE, &tmA, kt * BK, r, m0, full);
            }
            const float* src = Wg + (size_t)(kt * BK) * OUT_D;
            uint32_t dst = sb + SM_B + s * B_STAGE + lane * 16;
            #pragma unroll 8
            for (int i = 0; i < BK; i++)
                cp16(dst + i * (BPAD * 4), src + (size_t)i * OUT_D);
            CPASYNC_ARRIVE(full);
            if (++s == STG) { s = 0; u ^= 1; }
        }
    } else {
        // ---------------- consumer warps ----------------
        const int wm = wid & 3, wn = wid >> 2;
        const int g = lane >> 2, tg = lane & 3;

        float acc[2][8][4];
        #pragma unroll
        for (int mt = 0; mt < 2; mt++)
            #pragma unroll
            for (int nt = 0; nt < 8; nt++)
                #pragma unroll
                for (int i = 0; i < 4; i++)
                    acc[mt][nt][i] = 0.0f;

        const int arow = (wm * 32 + g) * 32;             // float offset of thread's A row
        const int boff = tg * BPAD + wn * 64 + g;        // float offset of thread's B base
        const int gx = g << 2;                           // swizzle xor (float units)

        int s = 0, u = 0;
        for (int kt = 0; kt < NK; kt++) {
            MBAR_WAIT(sb + CTRL + 8 * s, u);
            const float* Af = smf + s * (A_STAGE / 4) + arow;
            const float* Bf = smf + (SM_B / 4) + s * (B_STAGE / 4) + boff;

            #pragma unroll
            for (int ks = 0; ks < 4; ks++) {
                const int c0 = (8 * ks + tg) ^ gx;
                const int c1 = (8 * ks + tg + 4) ^ gx;
                uint32_t af[2][4];
                #pragma unroll
                for (int mt = 0; mt < 2; mt++) {
                    af[mt][0] = f2tf(Af[mt * 512 + c0]);
                    af[mt][1] = f2tf(Af[mt * 512 + 256 + c0]);
                    af[mt][2] = f2tf(Af[mt * 512 + c1]);
                    af[mt][3] = f2tf(Af[mt * 512 + 256 + c1]);
                }
                uint32_t bf[8][2];
                #pragma unroll
                for (int nt = 0; nt < 8; nt++) {
                    bf[nt][0] = __float_as_uint(Bf[ks * 8 * BPAD + nt * 8]);
                    bf[nt][1] = __float_as_uint(Bf[ks * 8 * BPAD + 4 * BPAD + nt * 8]);
                }
                #pragma unroll
                for (int mt = 0; mt < 2; mt++)
                    #pragma unroll
                    for (int nt = 0; nt < 8; nt++)
                        mma_tf32(acc[mt][nt], af[mt], bf[nt]);
            }
            if (lane == 0) MBARRIER_ARRIVE(sb + CTRL + 24 + 8 * s);
            if (++s == STG) { s = 0; u ^= 1; }
        }

        // ---------------- epilogue ----------------
        const float* bp = bias + (size_t)r * OUT_D + n0;
        #pragma unroll
        for (int mt = 0; mt < 2; mt++) {
            #pragma unroll
            for (int nt = 0; nt < 8; nt++) {
                int row0 = wm * 32 + mt * 16 + g;
                int col  = wn * 64 + nt * 8 + tg * 2;
                float b0 = bp[col];
                float b1 = bp[col + 1];
                float2 v0 = make_float2(acc[mt][nt][0] * KAPPA + b0,
                                        acc[mt][nt][1] * KAPPA + b1);
                float2 v1 = make_float2(acc[mt][nt][2] * KAPPA + b0,
                                        acc[mt][nt][3] * KAPPA + b1);
                size_t o0 = ((size_t)(m0 + row0)     * ROWG + r) * OUT_D + n0 + col;
                size_t o1 = ((size_t)(m0 + row0 + 8) * ROWG + r) * OUT_D + n0 + col;
                *reinterpret_cast<float2*>(out + o0) = v0;
                *reinterpret_cast<float2*>(out + o1) = v1;
            }
        }
    }
}

// ---------------- host ----------------
typedef CUresult (*encode_fn_t)(CUtensorMap*, CUtensorMapDataType, cuuint32_t, void*,
                                const cuuint64_t*, const cuuint64_t*, const cuuint32_t*,
                                const cuuint32_t*, CUtensorMapInterleave, CUtensorMapSwizzle,
                                CUtensorMapL2promotion, CUtensorMapFloatOOBfill);

extern "C" void kernel_launch(void* const* d_in, const int* in_sizes, int n_in,
                              void* d_out, int out_size) {
    const float* x    = (const float*)d_in[0];  // (512, 64, 1024)
    const float* W    = (const float*)d_in[1];  // (64, 1024, 1024)
    const float* bias = (const float*)d_in[2];  // (64, 1024)
    float* out = (float*)d_out;                 // (512, 64, 1024)

    encode_fn_t enc = nullptr;
    cudaDriverEntryPointQueryResult qr;
    cudaGetDriverEntryPointByVersion("cuTensorMapEncodeTiled", (void**)&enc, 12000,
                                     cudaEnableDefault, &qr);

    CUtensorMap tmA;
    {
        // x: dim0=i (contig), dim1=r, dim2=b ; box (BK, 1, BM), SW128
        cuuint64_t dims[3]    = {IN_DIM, ROWG, BATCH};
        cuuint64_t strides[2] = {IN_DIM * sizeof(float),
                                 (cuuint64_t)ROWG * IN_DIM * sizeof(float)};
        cuuint32_t box[3]     = {BK, 1, BM};
        cuuint32_t es[3]      = {1, 1, 1};
        enc(&tmA, CU_TENSOR_MAP_DATA_TYPE_FLOAT32, 3, (void*)x, dims, strides, box, es,
            CU_TENSOR_MAP_INTERLEAVE_NONE, CU_TENSOR_MAP_SWIZZLE_128B,
            CU_TENSOR_MAP_L2_PROMOTION_L2_128B, CU_TENSOR_MAP_FLOAT_OOB_FILL_NONE);
    }

    cudaFuncSetAttribute(gmlp_ws, cudaFuncAttributeMaxDynamicSharedMemorySize, SMEM_BYTES);
    dim3 grid(OUT_D / BN, BATCH / BM, ROWG);   // (8, 4, 64)
    gmlp_ws<<<grid, 288, SMEM_BYTES>>>(tmA, W, bias, out);
}